// round 9
// baseline (speedup 1.0000x reference)
#include <cuda_runtime.h>
#include <cstdint>
#include <math.h>

#define N_NODES 8192
#define FEAT    256
#define K1      25
#define K2      10

// Scratch (device globals — no allocation allowed)
__device__ int   g_nbr[N_NODES * K1];
__device__ int   g_cnt[N_NODES];
__device__ float g_s [N_NODES * FEAT];   // self branch:  lrelu(A@Wl^T + bl)
__device__ float g_yn[N_NODES * FEAT];   // raw nbr GEMM: A@Wn^T
__device__ float g_h1[N_NODES * FEAT];   // layer-1 output

__device__ __forceinline__ float lrelu(float x) {
    return x > 0.f ? x : 0.01f * x;
}

__device__ __forceinline__ unsigned f2tf(float x) {
    unsigned u;
    asm("cvt.rna.tf32.f32 %0, %1;" : "=r"(u) : "f"(x));
    return u;
}

__device__ __forceinline__ void mma_tf32(float* c,
    unsigned a0, unsigned a1, unsigned a2, unsigned a3,
    unsigned b0, unsigned b1)
{
    asm volatile(
        "mma.sync.aligned.m16n8k8.row.col.f32.tf32.tf32.f32 "
        "{%0,%1,%2,%3}, {%4,%5,%6,%7}, {%8,%9}, {%0,%1,%2,%3};"
        : "+f"(c[0]), "+f"(c[1]), "+f"(c[2]), "+f"(c[3])
        : "r"(a0), "r"(a1), "r"(a2), "r"(a3), "r"(b0), "r"(b1));
}

__device__ __forceinline__ void cp16(unsigned dst, const void* src) {
    asm volatile("cp.async.cg.shared.global [%0], [%1], 16;" :: "r"(dst), "l"(src));
}
__device__ __forceinline__ void cp_commit() {
    asm volatile("cp.async.commit_group;" ::: "memory");
}
__device__ __forceinline__ void cp_wait0() {
    asm volatile("cp.async.wait_group 0;" ::: "memory");
}

// ---------------------------------------------------------------------------
// Kernel 1: N-concatenated dual GEMM (one layer), both halves read the SAME A.
//   blockIdx.x < 4 : self half, W = Wl -> g_s  = lrelu(A@Wl^T + bl)
//   blockIdx.x >= 4: nbr  half, W = Wn -> g_yn = A@Wn^T          (raw)
// BM=128 BN=64 BK=32, 8 warps (4x2), warp tile 32x32, cp.async double buffer.
// (R4 configuration: plain launch_bounds(256), ~80 regs, 3 CTAs/SM)
// ---------------------------------------------------------------------------
template<int LAYER>
__global__ __launch_bounds__(256) void gemm_dual(
    const float* __restrict__ X,
    const float* __restrict__ Wl, const float* __restrict__ bl,
    const float* __restrict__ Wn)
{
    constexpr int BM = 128, BN = 64, BK = 32, NIT = FEAT / BK;
    __shared__ unsigned sA[2][BM * BK];
    __shared__ unsigned sB[2][BN * BK];

    int tid = threadIdx.x;
    bool self = blockIdx.x < 4;
    int n0 = (blockIdx.x & 3) * BN;
    int m0 = blockIdx.y * BM;

    const float* Abase = (LAYER == 1) ? X : (const float*)g_h1;
    const float* W     = self ? Wl : Wn;
    float* Out         = self ? g_s : g_yn;

    // loader mapping: A 4 chunks/thread, B 2 chunks/thread (16B chunks)
    int am  = tid >> 1, akc = (tid & 1) * 4;
    int bn_ = tid >> 2, bkc = (tid & 3) * 2;
    const float* pA = Abase + (size_t)(m0 + am)  * FEAT + akc * 4;
    const float* pB = W     + (size_t)(n0 + bn_) * FEAT + bkc * 4;
    unsigned baseA = (unsigned)__cvta_generic_to_shared(&sA[0][0]);
    unsigned baseB = (unsigned)__cvta_generic_to_shared(&sB[0][0]);
    unsigned dA = baseA + am  * (BK * 4);
    unsigned dB = baseB + bn_ * (BK * 4);
    int aswz = am  & 7, bswz = bn_ & 7;

    // fragment ids
    int warp = tid >> 5, lane = tid & 31;
    int wm = (warp >> 1) * 32, wn = (warp & 1) * 32;
    int group = lane >> 2, tig = lane & 3;

    float acc[2][4][4];
#pragma unroll
    for (int i = 0; i < 2; i++)
#pragma unroll
        for (int j = 0; j < 4; j++)
#pragma unroll
            for (int l = 0; l < 4; l++) acc[i][j][l] = 0.f;

#define ISSUE(st, k0)                                                          \
    {                                                                          \
        unsigned oa = dA + (st) * (BM * BK * 4);                               \
        const float* ga = pA + (k0);                                           \
        _Pragma("unroll")                                                      \
        for (int j = 0; j < 4; j++)                                            \
            cp16(oa + (((akc + j) ^ aswz) << 4), ga + j * 4);                  \
        unsigned ob = dB + (st) * (BN * BK * 4);                               \
        const float* gb = pB + (k0);                                           \
        _Pragma("unroll")                                                      \
        for (int j = 0; j < 2; j++)                                            \
            cp16(ob + (((bkc + j) ^ bswz) << 4), gb + j * 4);                  \
        cp_commit();                                                           \
    }

#define LDA(st, m, k) sA[st][(m) * BK + (((((k) >> 2) ^ ((m) & 7)) << 2) | ((k) & 3))]
#define LDB(st, n, k) sB[st][(n) * BK + (((((k) >> 2) ^ ((n) & 7)) << 2) | ((k) & 3))]

    ISSUE(0, 0);

    int st = 0;
    for (int it = 0; it < NIT; it++) {
        cp_wait0();
        __syncthreads();
        if (it + 1 < NIT) ISSUE(st ^ 1, (it + 1) * BK);
#pragma unroll
        for (int kk = 0; kk < BK; kk += 8) {
            int ka = kk + tig;
            unsigned af[2][4], bf[4][2];
#pragma unroll
            for (int mi = 0; mi < 2; mi++) {
                int r = wm + mi * 16 + group;
                af[mi][0] = LDA(st, r,     ka);
                af[mi][1] = LDA(st, r + 8, ka);
                af[mi][2] = LDA(st, r,     ka + 4);
                af[mi][3] = LDA(st, r + 8, ka + 4);
            }
#pragma unroll
            for (int ni = 0; ni < 4; ni++) {
                int n = wn + ni * 8 + group;
                bf[ni][0] = LDB(st, n, ka);
                bf[ni][1] = LDB(st, n, ka + 4);
            }
#pragma unroll
            for (int mi = 0; mi < 2; mi++)
#pragma unroll
                for (int ni = 0; ni < 4; ni++)
                    mma_tf32(acc[mi][ni], af[mi][0], af[mi][1], af[mi][2], af[mi][3],
                             bf[ni][0], bf[ni][1]);
        }
        st ^= 1;
    }

    // epilogue: self half gets bias+lrelu, yn half is raw
#pragma unroll
    for (int mi = 0; mi < 2; mi++) {
#pragma unroll
        for (int half = 0; half < 2; half++) {
            int row = m0 + wm + mi * 16 + group + half * 8;
#pragma unroll
            for (int ni = 0; ni < 4; ni++) {
                int col = n0 + wn + ni * 8 + tig * 2;
                float v0 = acc[mi][ni][half * 2 + 0];
                float v1 = acc[mi][ni][half * 2 + 1];
                if (self) {
                    v0 = lrelu(v0 + __ldg(bl + col));
                    v1 = lrelu(v1 + __ldg(bl + col + 1));
                }
                *(float2*)(Out + (size_t)row * FEAT + col) = make_float2(v0, v1);
            }
        }
    }
#undef ISSUE
#undef LDA
#undef LDB
}

// ---------------------------------------------------------------------------
// Kernel 2: FUSED neighbor-scan + layer-1 combine.
// Each warp: (a) ballot prefix-scans its node's adjacency row (early exit),
// writes g_nbr/g_cnt (needed later by final_fused), (b) gathers the first
// min(cnt,25) rows of g_yn (8 floats/lane, 5 accumulator chains), and writes
//   h1 = g_s + (cnt>0 ? lrelu(mean + bn1) : 0).
// 256 threads = 8 warps = 8 nodes per block; grid = 1024.
// ---------------------------------------------------------------------------
__global__ __launch_bounds__(256) void nbr_comb1(
    const int* __restrict__ A, const float* __restrict__ bn,
    float* __restrict__ OutH)
{
    __shared__ int s_nbr[8][K1];

    int tid = threadIdx.x;
    int w = tid >> 5, lane = tid & 31;
    int node = blockIdx.x * 8 + w;

    // ---- phase A: scan ----
    const int* row = A + (size_t)node * N_NODES;
    int found = 0;
    for (int c = 0; c < N_NODES && found < K1; c += 32) {
        int v = __ldg(row + c + lane);
        unsigned m = __ballot_sync(0xffffffffu, v > 0);
        if (v > 0) {
            int r = found + __popc(m & ((1u << lane) - 1u));
            if (r < K1) {
                s_nbr[w][r] = c + lane;
                g_nbr[node * K1 + r] = c + lane;
            }
        }
        found += __popc(m);
    }
    int cnt = found < K1 ? found : K1;
    if (lane < K1 && lane >= cnt) {
        s_nbr[w][lane] = 0;                 // safe dummy
        g_nbr[node * K1 + lane] = 0;
    }
    if (lane == 0) g_cnt[node] = cnt;
    __syncwarp();

    // ---- phase B: gather-mean + combine (same warp, own node) ----
    int c8 = lane * 8;
    int idx[K1];
#pragma unroll
    for (int t = 0; t < K1; t++) idx[t] = s_nbr[w][t];

    float4 a0[5], a1[5];
#pragma unroll
    for (int i = 0; i < 5; i++) {
        a0[i] = make_float4(0.f, 0.f, 0.f, 0.f);
        a1[i] = make_float4(0.f, 0.f, 0.f, 0.f);
    }
#pragma unroll
    for (int t = 0; t < K1; t++) {
        if (t < cnt) {
            const float* p = g_yn + (size_t)idx[t] * FEAT + c8;
            float4 v0 = *(const float4*)p;
            float4 v1 = *(const float4*)(p + 4);
            int ch = t % 5;
            a0[ch].x += v0.x; a0[ch].y += v0.y; a0[ch].z += v0.z; a0[ch].w += v0.w;
            a1[ch].x += v1.x; a1[ch].y += v1.y; a1[ch].z += v1.z; a1[ch].w += v1.w;
        }
    }
    float4 q0 = make_float4(0.f, 0.f, 0.f, 0.f);
    float4 q1 = make_float4(0.f, 0.f, 0.f, 0.f);
#pragma unroll
    for (int i = 0; i < 5; i++) {
        q0.x += a0[i].x; q0.y += a0[i].y; q0.z += a0[i].z; q0.w += a0[i].w;
        q1.x += a1[i].x; q1.y += a1[i].y; q1.z += a1[i].z; q1.w += a1[i].w;
    }

    float inv = (cnt > 0) ? (1.0f / (float)cnt) : 0.f;
    const float* ps = g_s + (size_t)node * FEAT + c8;
    float4 s0 = *(const float4*)ps;
    float4 s1 = *(const float4*)(ps + 4);
    float4 b0 = *(const float4*)(bn + c8);
    float4 b1 = *(const float4*)(bn + c8 + 4);
    float4 o0, o1;
    if (cnt > 0) {
        o0.x = s0.x + lrelu(q0.x * inv + b0.x);
        o0.y = s0.y + lrelu(q0.y * inv + b0.y);
        o0.z = s0.z + lrelu(q0.z * inv + b0.z);
        o0.w = s0.w + lrelu(q0.w * inv + b0.w);
        o1.x = s1.x + lrelu(q1.x * inv + b1.x);
        o1.y = s1.y + lrelu(q1.y * inv + b1.y);
        o1.z = s1.z + lrelu(q1.z * inv + b1.z);
        o1.w = s1.w + lrelu(q1.w * inv + b1.w);
    } else {
        o0 = s0; o1 = s1;
    }
    float* po = OutH + (size_t)node * FEAT + c8;
    *(float4*)po = o0;
    *(float4*)(po + 4) = o1;
}

// ---------------------------------------------------------------------------
// Kernel 3: fused layer-2 combine (pre-phase) + final GEMM + log_softmax.
// Pre-phase: 128 threads build the CTA's h2 tile (64 rows x 256) in dynamic
// smem:  h2 = g_s + (cnt>0 ? lrelu(mean10(g_yn) + bn2) : 0).
// GEMM phase: BM=64, 2x2 warps, warp tile 32x32, A read from the smem tile.
// h2tile row stride = 260 floats (65 16B-chunks, conflict-free).
// ---------------------------------------------------------------------------
#define H2_STRIDE 260
#define FINAL_DSMEM (64 * H2_STRIDE * 4)

__global__ __launch_bounds__(128) void final_fused(
    const float* __restrict__ bn2,
    const float* __restrict__ W3, const float* __restrict__ b3,
    float* __restrict__ OutP)
{
    constexpr int BM = 64, BN = 64, BK = 16;
    extern __shared__ float h2s[];          // [64][H2_STRIDE]

    __shared__ unsigned sA[BK][BM];
    __shared__ unsigned sB[BK][BN];
    __shared__ float sRes[BM][BN + 1];
    __shared__ float sLse[BM];

    int tid = threadIdx.x;
    int m0 = blockIdx.x * BM;

    // ---- pre-phase: build h2 tile ----
    {
        int row = tid & 63, half = tid >> 6;    // half: 0 or 1 -> cols 0/128
        int rowg = m0 + row;
        int cnt = __ldg(&g_cnt[rowg]); if (cnt > K2) cnt = K2;
        int idx[K2];
#pragma unroll
        for (int t = 0; t < K2; t++) idx[t] = __ldg(&g_nbr[rowg * K1 + t]);
        float inv = (cnt > 0) ? (1.0f / (float)cnt) : 0.f;

        int cbase = half * 128;
        const float* ps = g_s + (size_t)rowg * FEAT + cbase;
        float* pt = h2s + row * H2_STRIDE + cbase;
#pragma unroll 4
        for (int j = 0; j < 32; j++) {
            int c = cbase + j * 4;
            float4 q0 = make_float4(0.f, 0.f, 0.f, 0.f);
            float4 q1 = make_float4(0.f, 0.f, 0.f, 0.f);
#pragma unroll
            for (int t = 0; t < K2; t++) {
                if (t < cnt) {
                    float4 v = *(const float4*)(g_yn + (size_t)idx[t] * FEAT + c);
                    if (t & 1) { q1.x += v.x; q1.y += v.y; q1.z += v.z; q1.w += v.w; }
                    else       { q0.x += v.x; q0.y += v.y; q0.z += v.z; q0.w += v.w; }
                }
            }
            float4 s4 = *(const float4*)(ps + j * 4);
            float4 o;
            if (cnt > 0) {
                float4 b4 = *(const float4*)(bn2 + c);
                o.x = s4.x + lrelu((q0.x + q1.x) * inv + b4.x);
                o.y = s4.y + lrelu((q0.y + q1.y) * inv + b4.y);
                o.z = s4.z + lrelu((q0.z + q1.z) * inv + b4.z);
                o.w = s4.w + lrelu((q0.w + q1.w) * inv + b4.w);
            } else {
                o = s4;
            }
            *(float4*)(pt + j * 4) = o;
        }
    }
    __syncthreads();

    // ---- GEMM phase ----
    int am = tid & 63, ak = (tid >> 6) * 8;
    const float* pA = h2s + am * H2_STRIDE + ak;     // smem source
    const float* pB = W3 + (size_t)am * FEAT + ak;

    int warp = tid >> 5, lane = tid & 31;
    int wm = (warp >> 1) * 32, wn = (warp & 1) * 32;
    int group = lane >> 2, tig = lane & 3;
    int sw = tig << 3;

    float acc[2][4][4];
#pragma unroll
    for (int i = 0; i < 2; i++)
#pragma unroll
        for (int j = 0; j < 4; j++)
#pragma unroll
            for (int l = 0; l < 4; l++) acc[i][j][l] = 0.f;

    for (int k0 = 0; k0 < FEAT; k0 += BK) {
        float4 a0v = *(const float4*)(pA + k0);
        float4 a1v = *(const float4*)(pA + k0 + 4);
        float4 b0v = *(const float4*)(pB + k0);
        float4 b1v = *(const float4*)(pB + k0 + 4);
        __syncthreads();
        sA[ak + 0][am ^ 0 ] = f2tf(a0v.x); sA[ak + 1][am ^ 8 ] = f2tf(a0v.y);
        sA[ak + 2][am ^ 16] = f2tf(a0v.z); sA[ak + 3][am ^ 24] = f2tf(a0v.w);
        sA[ak + 4][am ^ 0 ] = f2tf(a1v.x); sA[ak + 5][am ^ 8 ] = f2tf(a1v.y);
        sA[ak + 6][am ^ 16] = f2tf(a1v.z); sA[ak + 7][am ^ 24] = f2tf(a1v.w);
        sB[ak + 0][am ^ 0 ] = f2tf(b0v.x); sB[ak + 1][am ^ 8 ] = f2tf(b0v.y);
        sB[ak + 2][am ^ 16] = f2tf(b0v.z); sB[ak + 3][am ^ 24] = f2tf(b0v.w);
        sB[ak + 4][am ^ 0 ] = f2tf(b1v.x); sB[ak + 5][am ^ 8 ] = f2tf(b1v.y);
        sB[ak + 6][am ^ 16] = f2tf(b1v.z); sB[ak + 7][am ^ 24] = f2tf(b1v.w);
        __syncthreads();
#pragma unroll
        for (int kk = 0; kk < BK; kk += 8) {
            int kA = kk + tig;
            unsigned af[2][4], bf[4][2];
#pragma unroll
            for (int mi = 0; mi < 2; mi++) {
                int r = wm + mi * 16 + group;
                af[mi][0] = sA[kA    ][r       ^ sw];
                af[mi][1] = sA[kA    ][(r + 8) ^ sw];
                af[mi][2] = sA[kA + 4][r       ^ sw];
                af[mi][3] = sA[kA + 4][(r + 8) ^ sw];
            }
#pragma unroll
            for (int ni = 0; ni < 4; ni++) {
                int c = (wn + ni * 8 + group) ^ sw;
                bf[ni][0] = sB[kA    ][c];
                bf[ni][1] = sB[kA + 4][c];
            }
#pragma unroll
            for (int mi = 0; mi < 2; mi++)
#pragma unroll
                for (int ni = 0; ni < 4; ni++)
                    mma_tf32(acc[mi][ni], af[mi][0], af[mi][1], af[mi][2], af[mi][3],
                             bf[ni][0], bf[ni][1]);
        }
    }

#pragma unroll
    for (int mi = 0; mi < 2; mi++)
#pragma unroll
        for (int half = 0; half < 2; half++) {
            int r = wm + mi * 16 + group + half * 8;
#pragma unroll
            for (int ni = 0; ni < 4; ni++) {
                int col = wn + ni * 8 + tig * 2;
                sRes[r][col]     = acc[mi][ni][half * 2 + 0] + __ldg(b3 + col);
                sRes[r][col + 1] = acc[mi][ni][half * 2 + 1] + __ldg(b3 + col + 1);
            }
        }
    __syncthreads();

    // log-softmax: 2 threads per row, 32 cols each, combine via shfl
    {
        int row = tid >> 1, half = tid & 1;
        int cbase = half * 32;
        float mx = -1e30f;
#pragma unroll 8
        for (int c = 0; c < 32; c++) mx = fmaxf(mx, sRes[row][cbase + c]);
        float omx = __shfl_xor_sync(0xffffffffu, mx, 1);
        mx = fmaxf(mx, omx);
        float s = 0.f;
#pragma unroll 8
        for (int c = 0; c < 32; c++) s += expf(sRes[row][cbase + c] - mx);
        s += __shfl_xor_sync(0xffffffffu, s, 1);
        if (half == 0) sLse[row] = mx + logf(s);
    }
    __syncthreads();

    for (int idx = tid; idx < BM * 64; idx += 128) {
        int r = idx >> 6, c = idx & 63;
        OutP[(size_t)(m0 + r) * 64 + c] = sRes[r][c] - sLse[r];
    }
}

// ---------------------------------------------------------------------------
extern "C" void kernel_launch(void* const* d_in, const int* in_sizes, int n_in,
                              void* d_out, int out_size) {
    const float* X   = (const float*)d_in[0];
    const int*   A   = (const int*)  d_in[1];
    const float* Wn1 = (const float*)d_in[2];
    const float* bn1 = (const float*)d_in[3];
    const float* Wl1 = (const float*)d_in[4];
    const float* bl1 = (const float*)d_in[5];
    const float* Wn2 = (const float*)d_in[6];
    const float* bn2 = (const float*)d_in[7];
    const float* Wl2 = (const float*)d_in[8];
    const float* bl2 = (const float*)d_in[9];
    const float* W3  = (const float*)d_in[10];
    const float* b3  = (const float*)d_in[11];
    float* out = (float*)d_out;

    cudaFuncSetAttribute(final_fused, cudaFuncAttributeMaxDynamicSharedMemorySize,
                         FINAL_DSMEM);

    float* h1p; cudaGetSymbolAddress((void**)&h1p, g_h1);

    dim3 ggrid(8, N_NODES / 128);   // 8 n-tiles (4 self + 4 yn) x 64 m-tiles

    // layer 1: dual GEMM, then fused scan+combine
    gemm_dual<1><<<ggrid, 256>>>(X, Wl1, bl1, Wn1);
    nbr_comb1<<<N_NODES / 8, 256>>>(A, bn1, h1p);

    // layer 2: dual GEMM (combine happens inside final_fused)
    gemm_dual<2><<<ggrid, 256>>>(X, Wl2, bl2, Wn2);

    // classifier: fused layer-2 combine + GEMM + log_softmax
    final_fused<<<N_NODES / 64, 128, FINAL_DSMEM>>>(bn2, W3, b3, out);
}

// round 10
// speedup vs baseline: 1.1020x; 1.1020x over previous
#include <cuda_runtime.h>
#include <cstdint>
#include <math.h>

#define N_NODES 8192
#define FEAT    256
#define K1      25
#define K2      10

// Scratch (device globals — no allocation allowed)
__device__ int   g_nbr[N_NODES * K1];
__device__ int   g_cnt[N_NODES];
__device__ float g_s [N_NODES * FEAT];   // self branch:  lrelu(A@Wl^T + bl)
__device__ float g_yn[N_NODES * FEAT];   // raw nbr GEMM: A@Wn^T
__device__ float g_h1[N_NODES * FEAT];   // layer-1 output
__device__ float g_h2[N_NODES * FEAT];   // layer-2 output

__device__ __forceinline__ float lrelu(float x) {
    return x > 0.f ? x : 0.01f * x;
}

__device__ __forceinline__ unsigned f2tf(float x) {
    unsigned u;
    asm("cvt.rna.tf32.f32 %0, %1;" : "=r"(u) : "f"(x));
    return u;
}

__device__ __forceinline__ void mma_tf32(float* c,
    unsigned a0, unsigned a1, unsigned a2, unsigned a3,
    unsigned b0, unsigned b1)
{
    asm volatile(
        "mma.sync.aligned.m16n8k8.row.col.f32.tf32.tf32.f32 "
        "{%0,%1,%2,%3}, {%4,%5,%6,%7}, {%8,%9}, {%0,%1,%2,%3};"
        : "+f"(c[0]), "+f"(c[1]), "+f"(c[2]), "+f"(c[3])
        : "r"(a0), "r"(a1), "r"(a2), "r"(a3), "r"(b0), "r"(b1));
}

__device__ __forceinline__ void cp16(unsigned dst, const void* src) {
    asm volatile("cp.async.cg.shared.global [%0], [%1], 16;" :: "r"(dst), "l"(src));
}
__device__ __forceinline__ void cp_commit() {
    asm volatile("cp.async.commit_group;" ::: "memory");
}
__device__ __forceinline__ void cp_wait0() {
    asm volatile("cp.async.wait_group 0;" ::: "memory");
}

// ---------------------------------------------------------------------------
// Kernel 1: N-concatenated dual GEMM (one layer), both halves read the SAME A.
//   blockIdx.x < 4 : self half, W = Wl -> g_s  = lrelu(A@Wl^T + bl)
//   blockIdx.x >= 4: nbr  half, W = Wn -> g_yn = A@Wn^T          (raw)
// BM=128 BN=64 BK=32, 8 warps (4x2), warp tile 32x32, cp.async double buffer.
// ---------------------------------------------------------------------------
template<int LAYER>
__global__ __launch_bounds__(256) void gemm_dual(
    const float* __restrict__ X,
    const float* __restrict__ Wl, const float* __restrict__ bl,
    const float* __restrict__ Wn)
{
    constexpr int BM = 128, BN = 64, BK = 32, NIT = FEAT / BK;
    __shared__ unsigned sA[2][BM * BK];
    __shared__ unsigned sB[2][BN * BK];

    int tid = threadIdx.x;
    bool self = blockIdx.x < 4;
    int n0 = (blockIdx.x & 3) * BN;
    int m0 = blockIdx.y * BM;

    const float* Abase = (LAYER == 1) ? X : (const float*)g_h1;
    const float* W     = self ? Wl : Wn;
    float* Out         = self ? g_s : g_yn;

    // loader mapping: A 4 chunks/thread, B 2 chunks/thread (16B chunks)
    int am  = tid >> 1, akc = (tid & 1) * 4;
    int bn_ = tid >> 2, bkc = (tid & 3) * 2;
    const float* pA = Abase + (size_t)(m0 + am)  * FEAT + akc * 4;
    const float* pB = W     + (size_t)(n0 + bn_) * FEAT + bkc * 4;
    unsigned baseA = (unsigned)__cvta_generic_to_shared(&sA[0][0]);
    unsigned baseB = (unsigned)__cvta_generic_to_shared(&sB[0][0]);
    unsigned dA = baseA + am  * (BK * 4);
    unsigned dB = baseB + bn_ * (BK * 4);
    int aswz = am  & 7, bswz = bn_ & 7;

    // fragment ids
    int warp = tid >> 5, lane = tid & 31;
    int wm = (warp >> 1) * 32, wn = (warp & 1) * 32;
    int group = lane >> 2, tig = lane & 3;

    float acc[2][4][4];
#pragma unroll
    for (int i = 0; i < 2; i++)
#pragma unroll
        for (int j = 0; j < 4; j++)
#pragma unroll
            for (int l = 0; l < 4; l++) acc[i][j][l] = 0.f;

#define ISSUE(st, k0)                                                          \
    {                                                                          \
        unsigned oa = dA + (st) * (BM * BK * 4);                               \
        const float* ga = pA + (k0);                                           \
        _Pragma("unroll")                                                      \
        for (int j = 0; j < 4; j++)                                            \
            cp16(oa + (((akc + j) ^ aswz) << 4), ga + j * 4);                  \
        unsigned ob = dB + (st) * (BN * BK * 4);                               \
        const float* gb = pB + (k0);                                           \
        _Pragma("unroll")                                                      \
        for (int j = 0; j < 2; j++)                                            \
            cp16(ob + (((bkc + j) ^ bswz) << 4), gb + j * 4);                  \
        cp_commit();                                                           \
    }

#define LDA(st, m, k) sA[st][(m) * BK + (((((k) >> 2) ^ ((m) & 7)) << 2) | ((k) & 3))]
#define LDB(st, n, k) sB[st][(n) * BK + (((((k) >> 2) ^ ((n) & 7)) << 2) | ((k) & 3))]

    ISSUE(0, 0);

    int st = 0;
    for (int it = 0; it < NIT; it++) {
        cp_wait0();
        __syncthreads();
        if (it + 1 < NIT) ISSUE(st ^ 1, (it + 1) * BK);
#pragma unroll
        for (int kk = 0; kk < BK; kk += 8) {
            int ka = kk + tig;
            unsigned af[2][4], bf[4][2];
#pragma unroll
            for (int mi = 0; mi < 2; mi++) {
                int r = wm + mi * 16 + group;
                af[mi][0] = LDA(st, r,     ka);
                af[mi][1] = LDA(st, r + 8, ka);
                af[mi][2] = LDA(st, r,     ka + 4);
                af[mi][3] = LDA(st, r + 8, ka + 4);
            }
#pragma unroll
            for (int ni = 0; ni < 4; ni++) {
                int n = wn + ni * 8 + group;
                bf[ni][0] = LDB(st, n, ka);
                bf[ni][1] = LDB(st, n, ka + 4);
            }
#pragma unroll
            for (int mi = 0; mi < 2; mi++)
#pragma unroll
                for (int ni = 0; ni < 4; ni++)
                    mma_tf32(acc[mi][ni], af[mi][0], af[mi][1], af[mi][2], af[mi][3],
                             bf[ni][0], bf[ni][1]);
        }
        st ^= 1;
    }

    // epilogue: self half gets bias+lrelu, yn half is raw
#pragma unroll
    for (int mi = 0; mi < 2; mi++) {
#pragma unroll
        for (int half = 0; half < 2; half++) {
            int row = m0 + wm + mi * 16 + group + half * 8;
#pragma unroll
            for (int ni = 0; ni < 4; ni++) {
                int col = n0 + wn + ni * 8 + tig * 2;
                float v0 = acc[mi][ni][half * 2 + 0];
                float v1 = acc[mi][ni][half * 2 + 1];
                if (self) {
                    v0 = lrelu(v0 + __ldg(bl + col));
                    v1 = lrelu(v1 + __ldg(bl + col + 1));
                }
                *(float2*)(Out + (size_t)row * FEAT + col) = make_float2(v0, v1);
            }
        }
    }
#undef ISSUE
#undef LDA
#undef LDB
}

// ---------------------------------------------------------------------------
// Kernel 2: FUSED neighbor-scan + layer-1 combine.
// Each warp: (a) ballot prefix-scans its node's adjacency row (early exit),
// writes g_nbr/g_cnt, (b) gathers the first min(cnt,25) rows of g_yn
// (8 floats/lane, 5 accumulator chains), writes
//   h1 = g_s + (cnt>0 ? lrelu(mean + bn1) : 0).
// ---------------------------------------------------------------------------
__global__ __launch_bounds__(256) void nbr_comb1(
    const int* __restrict__ A, const float* __restrict__ bn,
    float* __restrict__ OutH)
{
    __shared__ int s_nbr[8][K1];

    int tid = threadIdx.x;
    int w = tid >> 5, lane = tid & 31;
    int node = blockIdx.x * 8 + w;

    // ---- phase A: scan ----
    const int* row = A + (size_t)node * N_NODES;
    int found = 0;
    for (int c = 0; c < N_NODES && found < K1; c += 32) {
        int v = __ldg(row + c + lane);
        unsigned m = __ballot_sync(0xffffffffu, v > 0);
        if (v > 0) {
            int r = found + __popc(m & ((1u << lane) - 1u));
            if (r < K1) {
                s_nbr[w][r] = c + lane;
                g_nbr[node * K1 + r] = c + lane;
            }
        }
        found += __popc(m);
    }
    int cnt = found < K1 ? found : K1;
    if (lane < K1 && lane >= cnt) {
        s_nbr[w][lane] = 0;                 // safe dummy
        g_nbr[node * K1 + lane] = 0;
    }
    if (lane == 0) g_cnt[node] = cnt;
    __syncwarp();

    // ---- phase B: gather-mean + combine (same warp, own node) ----
    int c8 = lane * 8;
    int idx[K1];
#pragma unroll
    for (int t = 0; t < K1; t++) idx[t] = s_nbr[w][t];

    float4 a0[5], a1[5];
#pragma unroll
    for (int i = 0; i < 5; i++) {
        a0[i] = make_float4(0.f, 0.f, 0.f, 0.f);
        a1[i] = make_float4(0.f, 0.f, 0.f, 0.f);
    }
#pragma unroll
    for (int t = 0; t < K1; t++) {
        if (t < cnt) {
            const float* p = g_yn + (size_t)idx[t] * FEAT + c8;
            float4 v0 = *(const float4*)p;
            float4 v1 = *(const float4*)(p + 4);
            int ch = t % 5;
            a0[ch].x += v0.x; a0[ch].y += v0.y; a0[ch].z += v0.z; a0[ch].w += v0.w;
            a1[ch].x += v1.x; a1[ch].y += v1.y; a1[ch].z += v1.z; a1[ch].w += v1.w;
        }
    }
    float4 q0 = make_float4(0.f, 0.f, 0.f, 0.f);
    float4 q1 = make_float4(0.f, 0.f, 0.f, 0.f);
#pragma unroll
    for (int i = 0; i < 5; i++) {
        q0.x += a0[i].x; q0.y += a0[i].y; q0.z += a0[i].z; q0.w += a0[i].w;
        q1.x += a1[i].x; q1.y += a1[i].y; q1.z += a1[i].z; q1.w += a1[i].w;
    }

    float inv = (cnt > 0) ? (1.0f / (float)cnt) : 0.f;
    const float* ps = g_s + (size_t)node * FEAT + c8;
    float4 s0 = *(const float4*)ps;
    float4 s1 = *(const float4*)(ps + 4);
    float4 b0 = *(const float4*)(bn + c8);
    float4 b1 = *(const float4*)(bn + c8 + 4);
    float4 o0, o1;
    if (cnt > 0) {
        o0.x = s0.x + lrelu(q0.x * inv + b0.x);
        o0.y = s0.y + lrelu(q0.y * inv + b0.y);
        o0.z = s0.z + lrelu(q0.z * inv + b0.z);
        o0.w = s0.w + lrelu(q0.w * inv + b0.w);
        o1.x = s1.x + lrelu(q1.x * inv + b1.x);
        o1.y = s1.y + lrelu(q1.y * inv + b1.y);
        o1.z = s1.z + lrelu(q1.z * inv + b1.z);
        o1.w = s1.w + lrelu(q1.w * inv + b1.w);
    } else {
        o0 = s0; o1 = s1;
    }
    float* po = OutH + (size_t)node * FEAT + c8;
    *(float4*)po = o0;
    *(float4*)(po + 4) = o1;
}

// ---------------------------------------------------------------------------
// Kernel 3: layer-2 gather-mean + combine (separate, high grid parallelism):
//   h2 = g_s + (cnt>0 ? lrelu(mean10(g_yn) + bn2) : 0).
// 4 nodes / 256-thread block, float4/thread, 5 accumulator chains.
// ---------------------------------------------------------------------------
template <int K>
__global__ __launch_bounds__(256) void comb_kernel(
    const float* __restrict__ bn, float* __restrict__ OutH)
{
    int node = blockIdx.x * 4 + (threadIdx.x >> 6);
    int c4   = (threadIdx.x & 63) << 2;
    int cnt = g_cnt[node]; if (cnt > K) cnt = K;
    const int* nb = g_nbr + node * K1;

    const float* base[K];
#pragma unroll
    for (int t = 0; t < K; t++)
        base[t] = g_yn + (size_t)__ldg(nb + t) * FEAT + c4;

    float4 acc[5];
#pragma unroll
    for (int i = 0; i < 5; i++) acc[i] = make_float4(0.f, 0.f, 0.f, 0.f);

#pragma unroll
    for (int t = 0; t < K; t++) {
        if (t < cnt) {
            float4 v = *(const float4*)base[t];
            float4* a = &acc[t % 5];
            a->x += v.x; a->y += v.y; a->z += v.z; a->w += v.w;
        }
    }
    float sx = acc[0].x + acc[1].x + acc[2].x + acc[3].x + acc[4].x;
    float sy = acc[0].y + acc[1].y + acc[2].y + acc[3].y + acc[4].y;
    float sz = acc[0].z + acc[1].z + acc[2].z + acc[3].z + acc[4].z;
    float sw = acc[0].w + acc[1].w + acc[2].w + acc[3].w + acc[4].w;

    float inv = (cnt > 0) ? (1.0f / (float)cnt) : 0.f;
    float4 b4 = *(const float4*)(bn + c4);
    float4 s4 = *(const float4*)(g_s + (size_t)node * FEAT + c4);
    float4 o;
    if (cnt > 0) {
        o.x = s4.x + lrelu(sx * inv + b4.x);
        o.y = s4.y + lrelu(sy * inv + b4.y);
        o.z = s4.z + lrelu(sz * inv + b4.z);
        o.w = s4.w + lrelu(sw * inv + b4.w);
    } else {
        o = s4;
    }
    *(float4*)(OutH + (size_t)node * FEAT + c4) = o;
}

// ---------------------------------------------------------------------------
// Kernel 4: final GEMM [8192,256]x[256,64] (tf32 mma.sync) + fused log_softmax.
// BM=64, 128 threads (2x2 warps, warp tile 32x32), grid=128 CTAs.
// ---------------------------------------------------------------------------
__global__ __launch_bounds__(128) void final_kernel(
    const float* __restrict__ W3, const float* __restrict__ b3,
    float* __restrict__ OutP)
{
    constexpr int BM = 64, BN = 64, BK = 16;
    const float* __restrict__ H = (const float*)g_h2;

    __shared__ unsigned sA[BK][BM];
    __shared__ unsigned sB[BK][BN];
    __shared__ float sRes[BM][BN + 1];
    __shared__ float sLse[BM];

    int tid = threadIdx.x;
    int m0 = blockIdx.x * BM;
    int am = tid & 63, ak = (tid >> 6) * 8;
    const float* pA = H  + (size_t)(m0 + am) * FEAT + ak;
    const float* pB = W3 + (size_t)am * FEAT + ak;

    int warp = tid >> 5, lane = tid & 31;
    int wm = (warp >> 1) * 32, wn = (warp & 1) * 32;
    int group = lane >> 2, tig = lane & 3;
    int sw = tig << 3;

    float acc[2][4][4];
#pragma unroll
    for (int i = 0; i < 2; i++)
#pragma unroll
        for (int j = 0; j < 4; j++)
#pragma unroll
            for (int l = 0; l < 4; l++) acc[i][j][l] = 0.f;

    for (int k0 = 0; k0 < FEAT; k0 += BK) {
        float4 a0v = *(const float4*)(pA + k0);
        float4 a1v = *(const float4*)(pA + k0 + 4);
        float4 b0v = *(const float4*)(pB + k0);
        float4 b1v = *(const float4*)(pB + k0 + 4);
        __syncthreads();
        sA[ak + 0][am ^ 0 ] = f2tf(a0v.x); sA[ak + 1][am ^ 8 ] = f2tf(a0v.y);
        sA[ak + 2][am ^ 16] = f2tf(a0v.z); sA[ak + 3][am ^ 24] = f2tf(a0v.w);
        sA[ak + 4][am ^ 0 ] = f2tf(a1v.x); sA[ak + 5][am ^ 8 ] = f2tf(a1v.y);
        sA[ak + 6][am ^ 16] = f2tf(a1v.z); sA[ak + 7][am ^ 24] = f2tf(a1v.w);
        sB[ak + 0][am ^ 0 ] = f2tf(b0v.x); sB[ak + 1][am ^ 8 ] = f2tf(b0v.y);
        sB[ak + 2][am ^ 16] = f2tf(b0v.z); sB[ak + 3][am ^ 24] = f2tf(b0v.w);
        sB[ak + 4][am ^ 0 ] = f2tf(b1v.x); sB[ak + 5][am ^ 8 ] = f2tf(b1v.y);
        sB[ak + 6][am ^ 16] = f2tf(b1v.z); sB[ak + 7][am ^ 24] = f2tf(b1v.w);
        __syncthreads();
#pragma unroll
        for (int kk = 0; kk < BK; kk += 8) {
            int kA = kk + tig;
            unsigned af[2][4], bf[4][2];
#pragma unroll
            for (int mi = 0; mi < 2; mi++) {
                int r = wm + mi * 16 + group;
                af[mi][0] = sA[kA    ][r       ^ sw];
                af[mi][1] = sA[kA    ][(r + 8) ^ sw];
                af[mi][2] = sA[kA + 4][r       ^ sw];
                af[mi][3] = sA[kA + 4][(r + 8) ^ sw];
            }
#pragma unroll
            for (int ni = 0; ni < 4; ni++) {
                int c = (wn + ni * 8 + group) ^ sw;
                bf[ni][0] = sB[kA    ][c];
                bf[ni][1] = sB[kA + 4][c];
            }
#pragma unroll
            for (int mi = 0; mi < 2; mi++)
#pragma unroll
                for (int ni = 0; ni < 4; ni++)
                    mma_tf32(acc[mi][ni], af[mi][0], af[mi][1], af[mi][2], af[mi][3],
                             bf[ni][0], bf[ni][1]);
        }
    }

#pragma unroll
    for (int mi = 0; mi < 2; mi++)
#pragma unroll
        for (int half = 0; half < 2; half++) {
            int r = wm + mi * 16 + group + half * 8;
#pragma unroll
            for (int ni = 0; ni < 4; ni++) {
                int col = wn + ni * 8 + tig * 2;
                sRes[r][col]     = acc[mi][ni][half * 2 + 0] + __ldg(b3 + col);
                sRes[r][col + 1] = acc[mi][ni][half * 2 + 1] + __ldg(b3 + col + 1);
            }
        }
    __syncthreads();

    // log-softmax: 2 threads per row, 32 cols each, combine via shfl
    {
        int row = tid >> 1, half = tid & 1;
        int cbase = half * 32;
        float mx = -1e30f;
#pragma unroll 8
        for (int c = 0; c < 32; c++) mx = fmaxf(mx, sRes[row][cbase + c]);
        float omx = __shfl_xor_sync(0xffffffffu, mx, 1);
        mx = fmaxf(mx, omx);
        float s = 0.f;
#pragma unroll 8
        for (int c = 0; c < 32; c++) s += expf(sRes[row][cbase + c] - mx);
        s += __shfl_xor_sync(0xffffffffu, s, 1);
        if (half == 0) sLse[row] = mx + logf(s);
    }
    __syncthreads();

    for (int idx = tid; idx < BM * 64; idx += 128) {
        int r = idx >> 6, c = idx & 63;
        OutP[(size_t)(m0 + r) * 64 + c] = sRes[r][c] - sLse[r];
    }
}

// ---------------------------------------------------------------------------
extern "C" void kernel_launch(void* const* d_in, const int* in_sizes, int n_in,
                              void* d_out, int out_size) {
    const float* X   = (const float*)d_in[0];
    const int*   A   = (const int*)  d_in[1];
    const float* Wn1 = (const float*)d_in[2];
    const float* bn1 = (const float*)d_in[3];
    const float* Wl1 = (const float*)d_in[4];
    const float* bl1 = (const float*)d_in[5];
    const float* Wn2 = (const float*)d_in[6];
    const float* bn2 = (const float*)d_in[7];
    const float* Wl2 = (const float*)d_in[8];
    const float* bl2 = (const float*)d_in[9];
    const float* W3  = (const float*)d_in[10];
    const float* b3  = (const float*)d_in[11];
    float* out = (float*)d_out;

    float* h1p; cudaGetSymbolAddress((void**)&h1p, g_h1);
    float* h2p; cudaGetSymbolAddress((void**)&h2p, g_h2);

    dim3 ggrid(8, N_NODES / 128);   // 8 n-tiles (4 self + 4 yn) x 64 m-tiles

    // layer 1: dual GEMM, then fused scan+combine
    gemm_dual<1><<<ggrid, 256>>>(X, Wl1, bl1, Wn1);
    nbr_comb1<<<N_NODES / 8, 256>>>(A, bn1, h1p);

    // layer 2: dual GEMM, then separate combine (high grid parallelism)
    gemm_dual<2><<<ggrid, 256>>>(X, Wl2, bl2, Wn2);
    comb_kernel<K2><<<N_NODES / 4, 256>>>(bn2, h2p);

    // classifier + log_softmax
    final_kernel<<<N_NODES / 64, 128>>>(W3, b3, out);
}

// round 11
// speedup vs baseline: 1.1996x; 1.0885x over previous
#include <cuda_runtime.h>
#include <cstdint>
#include <math.h>

#define N_NODES 8192
#define FEAT    256
#define K1      25
#define K2      10

// Scratch (device globals — no allocation allowed)
__device__ int   g_nbr[N_NODES * K1];
__device__ int   g_cnt[N_NODES];
__device__ float g_s [N_NODES * FEAT];   // self branch:  lrelu(A@Wl^T + bl)
__device__ float g_yn[N_NODES * FEAT];   // raw nbr GEMM: A@Wn^T
__device__ float g_h1[N_NODES * FEAT];   // layer-1 output
__device__ float g_h2[N_NODES * FEAT];   // layer-2 output

// ---------------------------------------------------------------------------
// Kernel 1: first-K1 neighbor extraction (warp ballot prefix scan, early exit)
// ---------------------------------------------------------------------------
__global__ void nbr_kernel(const int* __restrict__ A) {
    int warp = (blockIdx.x * blockDim.x + threadIdx.x) >> 5;
    int lane = threadIdx.x & 31;
    if (warp >= N_NODES) return;
    const int* row = A + (size_t)warp * N_NODES;
    int found = 0;
    for (int c = 0; c < N_NODES && found < K1; c += 32) {
        int v = __ldg(row + c + lane);
        unsigned m = __ballot_sync(0xffffffffu, v > 0);
        if (v > 0) {
            int r = found + __popc(m & ((1u << lane) - 1u));
            if (r < K1) g_nbr[warp * K1 + r] = c + lane;
        }
        found += __popc(m);
    }
    int cnt = found < K1 ? found : K1;
    if (lane < K1 && lane >= cnt) g_nbr[warp * K1 + lane] = 0;  // safe dummy
    if (lane == 0) g_cnt[warp] = cnt;
}

__device__ __forceinline__ float lrelu(float x) {
    return x > 0.f ? x : 0.01f * x;
}

__device__ __forceinline__ unsigned f2tf(float x) {
    unsigned u;
    asm("cvt.rna.tf32.f32 %0, %1;" : "=r"(u) : "f"(x));
    return u;
}

__device__ __forceinline__ void mma_tf32(float* c,
    unsigned a0, unsigned a1, unsigned a2, unsigned a3,
    unsigned b0, unsigned b1)
{
    asm volatile(
        "mma.sync.aligned.m16n8k8.row.col.f32.tf32.tf32.f32 "
        "{%0,%1,%2,%3}, {%4,%5,%6,%7}, {%8,%9}, {%0,%1,%2,%3};"
        : "+f"(c[0]), "+f"(c[1]), "+f"(c[2]), "+f"(c[3])
        : "r"(a0), "r"(a1), "r"(a2), "r"(a3), "r"(b0), "r"(b1));
}

#define LDM_X4(r0, r1, r2, r3, addr)                                          \
    asm volatile("ldmatrix.sync.aligned.m8n8.x4.shared.b16 {%0,%1,%2,%3}, [%4];" \
        : "=r"(r0), "=r"(r1), "=r"(r2), "=r"(r3) : "r"(addr))

__device__ __forceinline__ void cp16(unsigned dst, const void* src) {
    asm volatile("cp.async.cg.shared.global [%0], [%1], 16;" :: "r"(dst), "l"(src));
}
__device__ __forceinline__ void cp_commit() {
    asm volatile("cp.async.commit_group;" ::: "memory");
}
__device__ __forceinline__ void cp_wait0() {
    asm volatile("cp.async.wait_group 0;" ::: "memory");
}

// ---------------------------------------------------------------------------
// Kernel 2: N-concatenated dual GEMM (one layer), both halves read the SAME A.
//   blockIdx.x < 4 : self half, W = Wl -> g_s  = lrelu(A@Wl^T + bl)
//   blockIdx.x >= 4: nbr  half, W = Wn -> g_yn = A@Wn^T          (raw)
// BM=128 BN=64 BK=32, 8 warps (4x2), warp tile 32x32, cp.async double buffer.
// Inner loop uses ldmatrix.x4 (tf32-as-b16 trick): 4 ldmatrix + 8 mma per k8.
// ---------------------------------------------------------------------------
template<int LAYER>
__global__ __launch_bounds__(256) void gemm_dual(
    const float* __restrict__ X,
    const float* __restrict__ Wl, const float* __restrict__ bl,
    const float* __restrict__ Wn)
{
    constexpr int BM = 128, BN = 64, BK = 32, NIT = FEAT / BK;
    __shared__ __align__(16) unsigned sA[2][BM * BK];
    __shared__ __align__(16) unsigned sB[2][BN * BK];

    int tid = threadIdx.x;
    bool self = blockIdx.x < 4;
    int n0 = (blockIdx.x & 3) * BN;
    int m0 = blockIdx.y * BM;

    const float* Abase = (LAYER == 1) ? X : (const float*)g_h1;
    const float* W     = self ? Wl : Wn;
    float* Out         = self ? g_s : g_yn;

    // loader mapping: A 4 chunks/thread, B 2 chunks/thread (16B chunks)
    int am  = tid >> 1, akc = (tid & 1) * 4;
    int bn_ = tid >> 2, bkc = (tid & 3) * 2;
    const float* pA = Abase + (size_t)(m0 + am)  * FEAT + akc * 4;
    const float* pB = W     + (size_t)(n0 + bn_) * FEAT + bkc * 4;
    unsigned baseA = (unsigned)__cvta_generic_to_shared(&sA[0][0]);
    unsigned baseB = (unsigned)__cvta_generic_to_shared(&sB[0][0]);
    unsigned dA = baseA + am  * (BK * 4);
    unsigned dB = baseB + bn_ * (BK * 4);
    int aswz = am  & 7, bswz = bn_ & 7;

    // fragment ids
    int warp = tid >> 5, lane = tid & 31;
    int wm = (warp >> 1) * 32, wn = (warp & 1) * 32;
    int group = lane >> 2, tig = lane & 3;

    // ldmatrix per-lane row/chunk assignments (swizzle key = lane&7 for all)
    int lrowA = lane & 15;          // row within a 16-row block
    int lselA = lane >> 4;          // 0 -> chunk c, 1 -> chunk c+1
    int lswz  = lane & 7;
    unsigned rowBaseA0 = baseA + (unsigned)((wm +  0 + lrowA) * BK) * 4u;
    unsigned rowBaseA1 = baseA + (unsigned)((wm + 16 + lrowA) * BK) * 4u;
    unsigned rowBaseB  = baseB + (unsigned)((wn + lane) * BK) * 4u;

    float acc[2][4][4];
#pragma unroll
    for (int i = 0; i < 2; i++)
#pragma unroll
        for (int j = 0; j < 4; j++)
#pragma unroll
            for (int l = 0; l < 4; l++) acc[i][j][l] = 0.f;

#define ISSUE(st, k0)                                                          \
    {                                                                          \
        unsigned oa = dA + (st) * (BM * BK * 4);                               \
        const float* ga = pA + (k0);                                           \
        _Pragma("unroll")                                                      \
        for (int j = 0; j < 4; j++)                                            \
            cp16(oa + (((akc + j) ^ aswz) << 4), ga + j * 4);                  \
        unsigned ob = dB + (st) * (BN * BK * 4);                               \
        const float* gb = pB + (k0);                                           \
        _Pragma("unroll")                                                      \
        for (int j = 0; j < 2; j++)                                            \
            cp16(ob + (((bkc + j) ^ bswz) << 4), gb + j * 4);                  \
        cp_commit();                                                           \
    }

    ISSUE(0, 0);

    int st = 0;
    for (int it = 0; it < NIT; it++) {
        cp_wait0();
        __syncthreads();
        if (it + 1 < NIT) ISSUE(st ^ 1, (it + 1) * BK);
        unsigned stA = (unsigned)st * (BM * BK * 4);
        unsigned stB = (unsigned)st * (BN * BK * 4);
#pragma unroll
        for (int kk = 0; kk < BK; kk += 8) {
            int c0 = kk >> 2;
            unsigned af[2][4], bf0[4], bf1[4];
            LDM_X4(af[0][0], af[0][1], af[0][2], af[0][3],
                   rowBaseA0 + stA + (unsigned)(((c0 + lselA) ^ lswz) << 4));
            LDM_X4(af[1][0], af[1][1], af[1][2], af[1][3],
                   rowBaseA1 + stA + (unsigned)(((c0 + lselA) ^ lswz) << 4));
            LDM_X4(bf0[0], bf0[1], bf0[2], bf0[3],
                   rowBaseB + stB + (unsigned)((c0 ^ lswz) << 4));
            LDM_X4(bf1[0], bf1[1], bf1[2], bf1[3],
                   rowBaseB + stB + (unsigned)(((c0 + 1) ^ lswz) << 4));
#pragma unroll
            for (int mi = 0; mi < 2; mi++)
#pragma unroll
                for (int ni = 0; ni < 4; ni++)
                    mma_tf32(acc[mi][ni], af[mi][0], af[mi][1], af[mi][2], af[mi][3],
                             bf0[ni], bf1[ni]);
        }
        st ^= 1;
    }

    // epilogue: self half gets bias+lrelu, yn half is raw
#pragma unroll
    for (int mi = 0; mi < 2; mi++) {
#pragma unroll
        for (int half = 0; half < 2; half++) {
            int row = m0 + wm + mi * 16 + group + half * 8;
#pragma unroll
            for (int ni = 0; ni < 4; ni++) {
                int col = n0 + wn + ni * 8 + tig * 2;
                float v0 = acc[mi][ni][half * 2 + 0];
                float v1 = acc[mi][ni][half * 2 + 1];
                if (self) {
                    v0 = lrelu(v0 + __ldg(bl + col));
                    v1 = lrelu(v1 + __ldg(bl + col + 1));
                }
                *(float2*)(Out + (size_t)row * FEAT + col) = make_float2(v0, v1);
            }
        }
    }
#undef ISSUE
}

// ---------------------------------------------------------------------------
// Kernel 3: gather-mean over first min(cnt,K) rows of g_yn + bias + lrelu,
// combined with the self branch:  h = g_s + (cnt>0 ? lrelu(mean + bn) : 0).
// 4 nodes / 256-thread block, float4/thread, dual accumulators (R4 version).
// ---------------------------------------------------------------------------
template <int K>
__global__ __launch_bounds__(256) void comb_kernel(
    const float* __restrict__ bn, float* __restrict__ OutH)
{
    int node = blockIdx.x * 4 + (threadIdx.x >> 6);
    int c4   = (threadIdx.x & 63) << 2;
    int cnt = g_cnt[node]; if (cnt > K) cnt = K;
    const int* nb = g_nbr + node * K1;

    int idx[K];
#pragma unroll
    for (int t = 0; t < K; t++) idx[t] = __ldg(nb + t);

    float4 a0 = make_float4(0.f, 0.f, 0.f, 0.f);
    float4 a1 = make_float4(0.f, 0.f, 0.f, 0.f);
#pragma unroll
    for (int t = 0; t < K; t += 2) {
        if (t < cnt) {
            float4 v = *(const float4*)(g_yn + (size_t)idx[t] * FEAT + c4);
            a0.x += v.x; a0.y += v.y; a0.z += v.z; a0.w += v.w;
        }
        if (t + 1 < cnt) {
            float4 v = *(const float4*)(g_yn + (size_t)idx[t + 1] * FEAT + c4);
            a1.x += v.x; a1.y += v.y; a1.z += v.z; a1.w += v.w;
        }
    }
    float inv = (cnt > 0) ? (1.0f / (float)cnt) : 0.f;
    float4 b4 = *(const float4*)(bn + c4);
    float4 s4 = *(const float4*)(g_s + (size_t)node * FEAT + c4);
    float4 o;
    if (cnt > 0) {
        o.x = s4.x + lrelu((a0.x + a1.x) * inv + b4.x);
        o.y = s4.y + lrelu((a0.y + a1.y) * inv + b4.y);
        o.z = s4.z + lrelu((a0.z + a1.z) * inv + b4.z);
        o.w = s4.w + lrelu((a0.w + a1.w) * inv + b4.w);
    } else {
        o = s4;
    }
    *(float4*)(OutH + (size_t)node * FEAT + c4) = o;
}

// ---------------------------------------------------------------------------
// Kernel 4: final GEMM [8192,256]x[256,64] (tf32 mma) + fused log_softmax.
// BM=128 covers full C=64 per CTA (R4 version, 256 threads).
// ---------------------------------------------------------------------------
__global__ __launch_bounds__(256) void final_kernel(
    const float* __restrict__ W3, const float* __restrict__ b3,
    float* __restrict__ OutP)
{
    constexpr int BM = 128, BN = 64, BK = 16;
    const float* __restrict__ H = (const float*)g_h2;

    __shared__ unsigned sA[BK][BM];
    __shared__ unsigned sB[BK][BN];
    __shared__ float sRes[BM][BN + 1];
    __shared__ float sLse[BM];

    int tid = threadIdx.x;
    int m0 = blockIdx.x * BM;
    int am = tid & 127, ak = (tid >> 7) * 8;
    int bn = tid & 63,  bk = (tid >> 6) * 4;
    const float* pA = H  + (size_t)(m0 + am) * FEAT + ak;
    const float* pB = W3 + (size_t)bn * FEAT + bk;

    int warp = tid >> 5, lane = tid & 31;
    int wm = (warp >> 1) * 32, wn = (warp & 1) * 32;
    int group = lane >> 2, tig = lane & 3;
    int sw = tig << 3;

    float acc[2][4][4];
#pragma unroll
    for (int i = 0; i < 2; i++)
#pragma unroll
        for (int j = 0; j < 4; j++)
#pragma unroll
            for (int l = 0; l < 4; l++) acc[i][j][l] = 0.f;

    for (int k0 = 0; k0 < FEAT; k0 += BK) {
        float4 a0v = *(const float4*)(pA + k0);
        float4 a1v = *(const float4*)(pA + k0 + 4);
        float4 bv  = *(const float4*)(pB + k0);
        __syncthreads();
        sA[ak + 0][am ^ 0 ] = f2tf(a0v.x); sA[ak + 1][am ^ 8 ] = f2tf(a0v.y);
        sA[ak + 2][am ^ 16] = f2tf(a0v.z); sA[ak + 3][am ^ 24] = f2tf(a0v.w);
        sA[ak + 4][am ^ 0 ] = f2tf(a1v.x); sA[ak + 5][am ^ 8 ] = f2tf(a1v.y);
        sA[ak + 6][am ^ 16] = f2tf(a1v.z); sA[ak + 7][am ^ 24] = f2tf(a1v.w);
        sB[bk + 0][bn ^ 0 ] = f2tf(bv.x);  sB[bk + 1][bn ^ 8 ] = f2tf(bv.y);
        sB[bk + 2][bn ^ 16] = f2tf(bv.z);  sB[bk + 3][bn ^ 24] = f2tf(bv.w);
        __syncthreads();
#pragma unroll
        for (int kk = 0; kk < BK; kk += 8) {
            int kA = kk + tig;
            unsigned af[2][4], bf[4][2];
#pragma unroll
            for (int mi = 0; mi < 2; mi++) {
                int r = wm + mi * 16 + group;
                af[mi][0] = sA[kA    ][r       ^ sw];
                af[mi][1] = sA[kA    ][(r + 8) ^ sw];
                af[mi][2] = sA[kA + 4][r       ^ sw];
                af[mi][3] = sA[kA + 4][(r + 8) ^ sw];
            }
#pragma unroll
            for (int ni = 0; ni < 4; ni++) {
                int c = (wn + ni * 8 + group) ^ sw;
                bf[ni][0] = sB[kA    ][c];
                bf[ni][1] = sB[kA + 4][c];
            }
#pragma unroll
            for (int mi = 0; mi < 2; mi++)
#pragma unroll
                for (int ni = 0; ni < 4; ni++)
                    mma_tf32(acc[mi][ni], af[mi][0], af[mi][1], af[mi][2], af[mi][3],
                             bf[ni][0], bf[ni][1]);
        }
    }

#pragma unroll
    for (int mi = 0; mi < 2; mi++)
#pragma unroll
        for (int half = 0; half < 2; half++) {
            int r = wm + mi * 16 + group + half * 8;
#pragma unroll
            for (int ni = 0; ni < 4; ni++) {
                int col = wn + ni * 8 + tig * 2;
                sRes[r][col]     = acc[mi][ni][half * 2 + 0] + __ldg(b3 + col);
                sRes[r][col + 1] = acc[mi][ni][half * 2 + 1] + __ldg(b3 + col + 1);
            }
        }
    __syncthreads();

    if (tid < BM) {
        float mx = -1e30f;
#pragma unroll 8
        for (int c = 0; c < 64; c++) mx = fmaxf(mx, sRes[tid][c]);
        float s = 0.f;
#pragma unroll 8
        for (int c = 0; c < 64; c++) s += expf(sRes[tid][c] - mx);
        sLse[tid] = mx + logf(s);
    }
    __syncthreads();

    for (int idx = tid; idx < BM * 64; idx += 256) {
        int r = idx >> 6, c = idx & 63;
        OutP[(size_t)(m0 + r) * 64 + c] = sRes[r][c] - sLse[r];
    }
}

// ---------------------------------------------------------------------------
extern "C" void kernel_launch(void* const* d_in, const int* in_sizes, int n_in,
                              void* d_out, int out_size) {
    const float* X   = (const float*)d_in[0];
    const int*   A   = (const int*)  d_in[1];
    const float* Wn1 = (const float*)d_in[2];
    const float* bn1 = (const float*)d_in[3];
    const float* Wl1 = (const float*)d_in[4];
    const float* bl1 = (const float*)d_in[5];
    const float* Wn2 = (const float*)d_in[6];
    const float* bn2 = (const float*)d_in[7];
    const float* Wl2 = (const float*)d_in[8];
    const float* bl2 = (const float*)d_in[9];
    const float* W3  = (const float*)d_in[10];
    const float* b3  = (const float*)d_in[11];
    float* out = (float*)d_out;

    float* h1p; cudaGetSymbolAddress((void**)&h1p, g_h1);
    float* h2p; cudaGetSymbolAddress((void**)&h2p, g_h2);

    dim3 ggrid(8, N_NODES / 128);   // 8 n-tiles (4 self + 4 yn) x 64 m-tiles

    // layer 1 GEMM depends only on X -> launch first
    gemm_dual<1><<<ggrid, 256>>>(X, Wl1, bl1, Wn1);
    nbr_kernel<<<N_NODES / 8, 256>>>(A);
    comb_kernel<K1><<<N_NODES / 4, 256>>>(bn1, h1p);

    // layer 2
    gemm_dual<2><<<ggrid, 256>>>(X, Wl2, bl2, Wn2);
    comb_kernel<K2><<<N_NODES / 4, 256>>>(bn2, h2p);

    // classifier + log_softmax
    final_kernel<<<N_NODES / 128, 256>>>(W3, b3, out);
}